// round 10
// baseline (speedup 1.0000x reference)
#include <cuda_runtime.h>
#include <cstdint>

// ---------------- problem constants ----------------
#define D        2048     // EMBED_DIM
#define VQD      256      // VQ_DIM
#define ATO      32000    // added_tokens_offset (text < ATO)
#define NUMLIM   33000    // ATO + SCO
#define TDLIM    33100    // VQ_START / image_token_offset
#define VQEND    49484    // vqgan_end_index
#define NTOK_MAX 65536

// ---------------- scratch (no allocations allowed) ----------------
__device__ int g_cnt;
__device__ int g_pos[NTOK_MAX];
__device__ int g_idx[NTOK_MAX];
__device__ __align__(16) float g_projT[VQD * D];   // [k][d] = proj_w[d][k]

typedef unsigned long long u64;

__device__ __forceinline__ u64 pack2(float lo, float hi) {
    u64 r; asm("mov.b64 %0, {%1,%2};" : "=l"(r) : "f"(lo), "f"(hi)); return r;
}
__device__ __forceinline__ void ffma2(u64 &d, u64 a, u64 b) {
    // packed fp32x2 FMA -> SASS FFMA2 (2x fp32 throughput on sm_103a)
    asm("fma.rn.f32x2 %0, %1, %2, %3;" : "=l"(d) : "l"(a), "l"(b), "l"(d));
}

// ---------------- launch 1: transpose proj_w + zero counter ----------------
__global__ void prep_kernel(const float* __restrict__ proj_w) {
    int i = blockIdx.x * blockDim.x + threadIdx.x;
    if (i == 0) g_cnt = 0;
    if (i < D * VQD) {
        int d = i >> 8;        // proj_w row (embed dim), row length 256
        int k = i & 255;       // vq dim
        g_projT[k * D + d] = proj_w[i];
    }
}

// ---------------- launch 2: classify + gather-copy (warp per token) ----------------
__global__ void classify_copy_kernel(const int* __restrict__ x,
                                     const float4* __restrict__ tok_emb,
                                     const float4* __restrict__ added_emb,
                                     const float4* __restrict__ nums_emb,
                                     float4* __restrict__ out, int n_tok) {
    int gw   = (blockIdx.x * blockDim.x + threadIdx.x) >> 5;   // token index
    int lane = threadIdx.x & 31;
    if (gw >= n_tok) return;
    int t = x[gw];

    const float4* src;
    if (t < ATO) {
        src = tok_emb + (size_t)t * (D / 4);
    } else if (t < NUMLIM) {
        src = nums_emb + (size_t)(t - ATO) * (D / 4);
    } else if (t < TDLIM) {
        src = added_emb + (size_t)(t - NUMLIM) * (D / 4);
    } else if (t < VQEND) {
        // image token: compact into list; GEMM kernel writes its output row
        if (lane == 0) {
            int s = atomicAdd(&g_cnt, 1);
            g_pos[s] = gw;
            g_idx[s] = t - TDLIM;
        }
        return;
    } else {
        src = nullptr;  // out-of-range -> zeros (unreachable with this data, but safe)
    }

    float4* dst = out + (size_t)gw * (D / 4);
    if (src) {
        #pragma unroll
        for (int i = 0; i < (D / 4) / 32; i++)      // 16 float4 per lane
            dst[lane + 32 * i] = src[lane + 32 * i];
    } else {
        float4 z = make_float4(0.f, 0.f, 0.f, 0.f);
        #pragma unroll
        for (int i = 0; i < (D / 4) / 32; i++)
            dst[lane + 32 * i] = z;
    }
}

// ---------------- launch 3: compacted image-token GEMM ----------------
// out[pos[i], :] = codebook[idx[i], :] (1x256)  @  proj_w^T (256x2048)
// Tile: 32 tokens x 256 dims per block; K = 256 in chunks of 8.
// Thread layout: tx = lane (dim group), ty = warp (token group, 4 tokens each).
// Each thread: 4 tokens x 8 dims, accumulated as 4x4 packed f32x2 FFMA2.
#define TT 32
#define TD 256

__global__ __launch_bounds__(256)
void img_gemm_kernel(const float* __restrict__ codebook, float* __restrict__ out,
                     int n_tile_tok) {
    __shared__ float As[TT * VQD];   // 32 KB: gathered codebook rows [token][k]
    __shared__ float Bs[8 * TD];     //  8 KB: projT chunk [kk][d]

    int n_img = g_cnt;
    int t0 = blockIdx.y * TT;
    if (t0 >= n_img) return;               // fixed grid; inactive tiles exit
    int dt = blockIdx.x * TD;

    int tid = threadIdx.x;
    int tx = tid & 31, ty = tid >> 5;

    // gather A: thread handles token tid>>3, segment tid&7 (32 floats = 8 float4)
    {
        int tokl = tid >> 3, seg = tid & 7;
        int gi = t0 + tokl;
        int idx = (gi < n_img) ? g_idx[gi] : 0;
        const float4* srow = (const float4*)(codebook + (size_t)idx * VQD) + seg * 8;
        float4* drow = (float4*)(As + tokl * VQD) + seg * 8;
        #pragma unroll
        for (int i = 0; i < 8; i++) drow[i] = srow[i];
    }

    u64 acc[4][4];
    #pragma unroll
    for (int j = 0; j < 4; j++)
        #pragma unroll
        for (int p = 0; p < 4; p++) acc[j][p] = 0ull;

    const float* bsrc = g_projT + dt;

    for (int k0 = 0; k0 < VQD; k0 += 8) {
        __syncthreads();                    // also orders the As gather (first iter)
        // load Bs[8][256]: 512 float4, 2 per thread, coalesced rows of projT
        #pragma unroll
        for (int i = 0; i < 2; i++) {
            int fi = tid + 256 * i;         // float4 index within chunk
            int kk = fi >> 6;               // 64 float4 per k-row
            int c4 = fi & 63;
            ((float4*)Bs)[fi] = *((const float4*)(bsrc + (size_t)(k0 + kk) * D) + c4);
        }
        __syncthreads();

        #pragma unroll
        for (int kk = 0; kk < 8; kk++) {
            const float* brow = Bs + kk * TD;
            // dims: {2tx, 2tx+1} + 64p  -> conflict-free LDS.64, coalesced STG.64
            u64 b0 = *(const u64*)(brow + 2 * tx);
            u64 b1 = *(const u64*)(brow + 2 * tx + 64);
            u64 b2 = *(const u64*)(brow + 2 * tx + 128);
            u64 b3 = *(const u64*)(brow + 2 * tx + 192);
            int k = k0 + kk;
            #pragma unroll
            for (int j = 0; j < 4; j++) {
                float a = As[(ty * 4 + j) * VQD + k];   // broadcast within warp
                u64 ap = pack2(a, a);
                ffma2(acc[j][0], ap, b0);
                ffma2(acc[j][1], ap, b1);
                ffma2(acc[j][2], ap, b2);
                ffma2(acc[j][3], ap, b3);
            }
        }
    }

    // epilogue: scatter rows to out
    #pragma unroll
    for (int j = 0; j < 4; j++) {
        int gi = t0 + ty * 4 + j;
        if (gi >= n_img) continue;
        int row = g_pos[gi];
        float* op = out + (size_t)row * D + dt;
        *(u64*)(op + 2 * tx)       = acc[j][0];
        *(u64*)(op + 2 * tx + 64)  = acc[j][1];
        *(u64*)(op + 2 * tx + 128) = acc[j][2];
        *(u64*)(op + 2 * tx + 192) = acc[j][3];
    }
}

// ---------------- launcher ----------------
extern "C" void kernel_launch(void* const* d_in, const int* in_sizes, int n_in,
                              void* d_out, int out_size) {
    const int*   x        = (const int*)d_in[0];
    const float* tok_emb  = (const float*)d_in[1];
    const float* added    = (const float*)d_in[2];
    const float* nums     = (const float*)d_in[3];
    const float* codebook = (const float*)d_in[4];
    const float* proj_w   = (const float*)d_in[5];
    float*       out      = (float*)d_out;
    int n_tok = in_sizes[0];                 // B*S = 32768

    prep_kernel<<<(D * VQD + 255) / 256, 256>>>(proj_w);

    classify_copy_kernel<<<(n_tok + 7) / 8, 256>>>(
        x, (const float4*)tok_emb, (const float4*)added,
        (const float4*)nums, (float4*)out, n_tok);

    int n_tile_tok = (n_tok + TT - 1) / TT;  // worst case: all tokens are images
    dim3 grid(D / TD, n_tile_tok);
    img_gemm_kernel<<<grid, 256>>>(codebook, out, n_tile_tok);
}

// round 11
// speedup vs baseline: 1.0012x; 1.0012x over previous
#include <cuda_runtime.h>
#include <cstdint>

// ---------------- problem constants ----------------
#define D        2048     // EMBED_DIM
#define VQD      256      // VQ_DIM
#define ATO      32000    // added_tokens_offset (text < ATO)
#define NUMLIM   33000    // ATO + SCO
#define TDLIM    33100    // VQ_START / image_token_offset
#define VQEND    49484    // vqgan_end_index
#define NTOK_MAX 65536

// ---------------- scratch (no allocations allowed) ----------------
__device__ int g_cnt;
__device__ int g_pos[NTOK_MAX];
__device__ int g_idx[NTOK_MAX];
__device__ __align__(16) float g_projT[VQD * D];   // [k][d] = proj_w[d][k]

typedef unsigned long long u64;

__device__ __forceinline__ u64 pack2(float lo, float hi) {
    u64 r; asm("mov.b64 %0, {%1,%2};" : "=l"(r) : "f"(lo), "f"(hi)); return r;
}
__device__ __forceinline__ void ffma2(u64 &d, u64 a, u64 b) {
    // packed fp32x2 FMA -> SASS FFMA2 (2x fp32 throughput on sm_103a)
    asm("fma.rn.f32x2 %0, %1, %2, %3;" : "=l"(d) : "l"(a), "l"(b), "l"(d));
}

// ---------------- launch 1: transpose proj_w + zero counter ----------------
__global__ void prep_kernel(const float* __restrict__ proj_w) {
    int i = blockIdx.x * blockDim.x + threadIdx.x;
    if (i == 0) g_cnt = 0;
    if (i < D * VQD) {
        int d = i >> 8;        // proj_w row (embed dim), row length 256
        int k = i & 255;       // vq dim
        g_projT[k * D + d] = proj_w[i];
    }
}

// ---------------- launch 2: classify + gather-copy (warp per token) ----------------
__global__ void classify_copy_kernel(const int* __restrict__ x,
                                     const float4* __restrict__ tok_emb,
                                     const float4* __restrict__ added_emb,
                                     const float4* __restrict__ nums_emb,
                                     float4* __restrict__ out, int n_tok) {
    int gw   = (blockIdx.x * blockDim.x + threadIdx.x) >> 5;   // token index
    int lane = threadIdx.x & 31;
    if (gw >= n_tok) return;
    int t = x[gw];

    const float4* src;
    if (t < ATO) {
        src = tok_emb + (size_t)t * (D / 4);
    } else if (t < NUMLIM) {
        src = nums_emb + (size_t)(t - ATO) * (D / 4);
    } else if (t < TDLIM) {
        src = added_emb + (size_t)(t - NUMLIM) * (D / 4);
    } else if (t < VQEND) {
        // image token: compact into list; GEMM kernel writes its output row
        if (lane == 0) {
            int s = atomicAdd(&g_cnt, 1);
            g_pos[s] = gw;
            g_idx[s] = t - TDLIM;
        }
        return;
    } else {
        src = nullptr;  // out-of-range -> zeros (unreachable with this data, but safe)
    }

    float4* dst = out + (size_t)gw * (D / 4);
    if (src) {
        #pragma unroll
        for (int i = 0; i < (D / 4) / 32; i++)      // 16 float4 per lane
            dst[lane + 32 * i] = src[lane + 32 * i];
    } else {
        float4 z = make_float4(0.f, 0.f, 0.f, 0.f);
        #pragma unroll
        for (int i = 0; i < (D / 4) / 32; i++)
            dst[lane + 32 * i] = z;
    }
}

// ---------------- launch 3: compacted image-token GEMM ----------------
// out[pos[i], :] = codebook[idx[i], :] (1x256)  @  proj_w^T (256x2048)
// Tile: 32 tokens x 256 dims per block; K = 256 in chunks of 8.
// Thread layout: tx = lane (dim group), ty = warp (token group, 4 tokens each).
// Each thread: 4 tokens x 8 dims, accumulated as 4x4 packed f32x2 FFMA2.
#define TT 32
#define TD 256

__global__ __launch_bounds__(256)
void img_gemm_kernel(const float* __restrict__ codebook, float* __restrict__ out,
                     int n_tile_tok) {
    __shared__ float As[TT * VQD];   // 32 KB: gathered codebook rows [token][k]
    __shared__ float Bs[8 * TD];     //  8 KB: projT chunk [kk][d]

    int n_img = g_cnt;
    int t0 = blockIdx.y * TT;
    if (t0 >= n_img) return;               // fixed grid; inactive tiles exit
    int dt = blockIdx.x * TD;

    int tid = threadIdx.x;
    int tx = tid & 31, ty = tid >> 5;

    // gather A: thread handles token tid>>3, segment tid&7 (32 floats = 8 float4)
    {
        int tokl = tid >> 3, seg = tid & 7;
        int gi = t0 + tokl;
        int idx = (gi < n_img) ? g_idx[gi] : 0;
        const float4* srow = (const float4*)(codebook + (size_t)idx * VQD) + seg * 8;
        float4* drow = (float4*)(As + tokl * VQD) + seg * 8;
        #pragma unroll
        for (int i = 0; i < 8; i++) drow[i] = srow[i];
    }

    u64 acc[4][4];
    #pragma unroll
    for (int j = 0; j < 4; j++)
        #pragma unroll
        for (int p = 0; p < 4; p++) acc[j][p] = 0ull;

    const float* bsrc = g_projT + dt;

    for (int k0 = 0; k0 < VQD; k0 += 8) {
        __syncthreads();                    // also orders the As gather (first iter)
        // load Bs[8][256]: 512 float4, 2 per thread, coalesced rows of projT
        #pragma unroll
        for (int i = 0; i < 2; i++) {
            int fi = tid + 256 * i;         // float4 index within chunk
            int kk = fi >> 6;               // 64 float4 per k-row
            int c4 = fi & 63;
            ((float4*)Bs)[fi] = *((const float4*)(bsrc + (size_t)(k0 + kk) * D) + c4);
        }
        __syncthreads();

        #pragma unroll
        for (int kk = 0; kk < 8; kk++) {
            const float* brow = Bs + kk * TD;
            // dims: {2tx, 2tx+1} + 64p  -> conflict-free LDS.64, coalesced STG.64
            u64 b0 = *(const u64*)(brow + 2 * tx);
            u64 b1 = *(const u64*)(brow + 2 * tx + 64);
            u64 b2 = *(const u64*)(brow + 2 * tx + 128);
            u64 b3 = *(const u64*)(brow + 2 * tx + 192);
            int k = k0 + kk;
            #pragma unroll
            for (int j = 0; j < 4; j++) {
                float a = As[(ty * 4 + j) * VQD + k];   // broadcast within warp
                u64 ap = pack2(a, a);
                ffma2(acc[j][0], ap, b0);
                ffma2(acc[j][1], ap, b1);
                ffma2(acc[j][2], ap, b2);
                ffma2(acc[j][3], ap, b3);
            }
        }
    }

    // epilogue: scatter rows to out
    #pragma unroll
    for (int j = 0; j < 4; j++) {
        int gi = t0 + ty * 4 + j;
        if (gi >= n_img) continue;
        int row = g_pos[gi];
        float* op = out + (size_t)row * D + dt;
        *(u64*)(op + 2 * tx)       = acc[j][0];
        *(u64*)(op + 2 * tx + 64)  = acc[j][1];
        *(u64*)(op + 2 * tx + 128) = acc[j][2];
        *(u64*)(op + 2 * tx + 192) = acc[j][3];
    }
}

// ---------------- launcher ----------------
extern "C" void kernel_launch(void* const* d_in, const int* in_sizes, int n_in,
                              void* d_out, int out_size) {
    const int*   x        = (const int*)d_in[0];
    const float* tok_emb  = (const float*)d_in[1];
    const float* added    = (const float*)d_in[2];
    const float* nums     = (const float*)d_in[3];
    const float* codebook = (const float*)d_in[4];
    const float* proj_w   = (const float*)d_in[5];
    float*       out      = (float*)d_out;
    int n_tok = in_sizes[0];                 // B*S = 32768

    prep_kernel<<<(D * VQD + 255) / 256, 256>>>(proj_w);

    classify_copy_kernel<<<(n_tok + 7) / 8, 256>>>(
        x, (const float4*)tok_emb, (const float4*)added,
        (const float4*)nums, (float4*)out, n_tok);

    int n_tile_tok = (n_tok + TT - 1) / TT;  // worst case: all tokens are images
    dim3 grid(D / TD, n_tile_tok);
    img_gemm_kernel<<<grid, 256>>>(codebook, out, n_tile_tok);
}

// round 15
// speedup vs baseline: 1.7252x; 1.7232x over previous
#include <cuda_runtime.h>
#include <cuda_bf16.h>
#include <cstdint>

// ---------------- problem constants ----------------
#define D        2048     // EMBED_DIM
#define VQD      256      // VQ_DIM
#define ATO      32000
#define NUMLIM   33000    // ATO + SCO
#define TDLIM    33100    // VQ_START / image_token_offset
#define VQEND    49484
#define NTOK_MAX 65536

// ---------------- scratch (no allocations allowed) ----------------
__device__ int g_cnt;
__device__ int g_pos[NTOK_MAX];
__device__ int g_idx[NTOK_MAX];
// proj_w split into bf16 hi/lo, layout [d][k] (k contiguous), packed 8 bf16
// per uint4. uint4 typing guarantees 16B alignment BY TYPE (the __align__
// attribute on a bf16 array was not honored -> misaligned address in R13/R14).
__device__ uint4 g_BH4[D * VQD / 8];
__device__ uint4 g_BL4[D * VQD / 8];

__device__ __forceinline__ uint32_t pbf2(float a, float b) {
    __nv_bfloat162 h = __floats2bfloat162_rn(a, b);
    return *(uint32_t*)&h;
}

// ---------------- launch 1: split proj_w -> bf16 hi/lo (packed) + zero counter ----------------
__global__ void split_kernel(const float4* __restrict__ proj_w4) {
    int i = blockIdx.x * blockDim.x + threadIdx.x;    // uint4 index (8 floats)
    if (i == 0) g_cnt = 0;
    if (i < D * VQD / 8) {
        float4 v0 = proj_w4[2 * i];
        float4 v1 = proj_w4[2 * i + 1];
        float f[8] = {v0.x, v0.y, v0.z, v0.w, v1.x, v1.y, v1.z, v1.w};
        uint32_t h[4], l[4];
        #pragma unroll
        for (int p = 0; p < 4; p++) {
            float a = f[2 * p], b = f[2 * p + 1];
            float ah = __bfloat162float(__float2bfloat16_rn(a));
            float bh = __bfloat162float(__float2bfloat16_rn(b));
            h[p] = pbf2(a, b);
            l[p] = pbf2(a - ah, b - bh);
        }
        g_BH4[i] = make_uint4(h[0], h[1], h[2], h[3]);
        g_BL4[i] = make_uint4(l[0], l[1], l[2], l[3]);
    }
}

// ---------------- launch 2: classify + gather-copy (warp per token) ----------------
__global__ void classify_copy_kernel(const int* __restrict__ x,
                                     const float4* __restrict__ tok_emb,
                                     const float4* __restrict__ added_emb,
                                     const float4* __restrict__ nums_emb,
                                     float4* __restrict__ out, int n_tok) {
    int gw   = (blockIdx.x * blockDim.x + threadIdx.x) >> 5;
    int lane = threadIdx.x & 31;
    if (gw >= n_tok) return;
    int t = x[gw];

    const float4* src;
    if (t < ATO) {
        src = tok_emb + (size_t)t * (D / 4);
    } else if (t < NUMLIM) {
        src = nums_emb + (size_t)(t - ATO) * (D / 4);
    } else if (t < TDLIM) {
        src = added_emb + (size_t)(t - NUMLIM) * (D / 4);
    } else if (t < VQEND) {
        if (lane == 0) {
            int s = atomicAdd(&g_cnt, 1);
            g_pos[s] = gw;
            g_idx[s] = t - TDLIM;
        }
        return;
    } else {
        src = nullptr;
    }

    float4* dst = out + (size_t)gw * (D / 4);
    if (src) {
        #pragma unroll
        for (int i = 0; i < (D / 4) / 32; i++)
            dst[lane + 32 * i] = src[lane + 32 * i];
    } else {
        float4 z = make_float4(0.f, 0.f, 0.f, 0.f);
        #pragma unroll
        for (int i = 0; i < (D / 4) / 32; i++)
            dst[lane + 32 * i] = z;
    }
}

// ---------------- launch 3: HMMA (mma.sync bf16, 3-term split) image GEMM ----------------
// Block: 64 tokens x 1024 dims (grid.x splits D in 2). Inner loop: 16 tiles of 64 dims.
// 8 warps as 2(m) x 4(n): warp tile m32 x n16. K = 256 in 16 k16-steps.
#define GT      64
#define NSPLIT  2
#define NBLK    (D / NSPLIT)   // 1024
#define NTILE   64

// smem plane offsets (bytes)
#define A_HI 0
#define A_LO 32768
#define B_HI 65536
#define B_LO 98304
#define SMEM_BYTES 131072

// XOR-swizzled offset within one 32KB plane: 64 rows x 256 k (bf16), stored as
// 4 k-chunks of 64; within a chunk, 8x16B groups per row, group ^= (row & 7).
__device__ __forceinline__ uint32_t sw_off(int row, int k) {
    return ((uint32_t)(k >> 6) << 13) + ((uint32_t)row << 7)
         + ((uint32_t)((((k >> 3) & 7) ^ (row & 7))) << 4) + ((uint32_t)(k & 7) << 1);
}

__device__ __forceinline__ uint32_t smem_u32(const void* p) {
    uint32_t a;
    asm("{ .reg .u64 t; cvta.to.shared.u64 t, %1; cvt.u32.u64 %0, t; }" : "=r"(a) : "l"(p));
    return a;
}
__device__ __forceinline__ void ldm4(uint32_t* r, uint32_t addr) {
    asm volatile("ldmatrix.sync.aligned.m8n8.x4.shared.b16 {%0,%1,%2,%3}, [%4];"
        : "=r"(r[0]), "=r"(r[1]), "=r"(r[2]), "=r"(r[3]) : "r"(addr));
}
__device__ __forceinline__ void mma16816(float* c, const uint32_t* a, const uint32_t* b) {
    asm volatile("mma.sync.aligned.m16n8k16.row.col.f32.bf16.bf16.f32 "
        "{%0,%1,%2,%3}, {%4,%5,%6,%7}, {%8,%9}, {%0,%1,%2,%3};"
        : "+f"(c[0]), "+f"(c[1]), "+f"(c[2]), "+f"(c[3])
        : "r"(a[0]), "r"(a[1]), "r"(a[2]), "r"(a[3]), "r"(b[0]), "r"(b[1]));
}

__global__ void __launch_bounds__(256, 1)
img_hmma_kernel(const float* __restrict__ codebook, float* __restrict__ out) {
    extern __shared__ __align__(16) char smem[];
    __shared__ int s_pos[GT];

    int n_img = g_cnt;
    int t0 = blockIdx.y * GT;
    if (t0 >= n_img) return;

    uint32_t sb = smem_u32(smem);
    int tid  = threadIdx.x;
    int lane = tid & 31;
    int wid  = tid >> 5;
    int wm   = wid >> 2;          // 0..1 -> m offset 0/32
    int wn   = wid & 3;           // 0..3 -> n offset 0/16/32/48

    if (tid < GT) {
        int gi = t0 + tid;
        s_pos[tid] = (gi < n_img) ? g_pos[gi] : -1;
    }

    // ---- gather A (codebook rows), split into bf16 hi/lo, swizzled smem ----
    #pragma unroll
    for (int i = 0; i < 8; i++) {
        int e  = tid + i * 256;           // 0..2047 ; each handles 8 floats
        int m  = e >> 5;                  // token within block
        int k0 = (e & 31) << 3;           // k start (mult of 8)
        int gi = t0 + m;
        int idx = (gi < n_img) ? g_idx[gi] : 0;
        const float4* src = (const float4*)(codebook + (size_t)idx * VQD + k0);
        float4 v0 = src[0];
        float4 v1 = src[1];
        float f[8] = {v0.x, v0.y, v0.z, v0.w, v1.x, v1.y, v1.z, v1.w};
        uint32_t h[4], l[4];
        #pragma unroll
        for (int p = 0; p < 4; p++) {
            float a = f[2 * p], b = f[2 * p + 1];
            float ah = __bfloat162float(__float2bfloat16_rn(a));
            float bh = __bfloat162float(__float2bfloat16_rn(b));
            h[p] = pbf2(a, b);
            l[p] = pbf2(a - ah, b - bh);
        }
        uint32_t o = sw_off(m, k0);
        *(uint4*)(smem + A_HI + o) = make_uint4(h[0], h[1], h[2], h[3]);
        *(uint4*)(smem + A_LO + o) = make_uint4(l[0], l[1], l[2], l[3]);
    }

    // per-lane ldmatrix address components
    int g = lane >> 3, r = lane & 7;
    int am_base = wm * 32 + ((g & 1) << 3) + r;       // A: g0/g2 -> m0-7, g1/g3 -> m8-15
    int ak_add  = (g >> 1) << 3;                      //    g2/g3 -> k+8
    int bn_base = wn * 16 + ((g >> 1) << 3) + r;      // B: g2/g3 -> n8-15
    int bk_add  = (g & 1) << 3;                       //    g1/g3 -> k+8

    for (int nt = 0; nt < NBLK / NTILE; nt++) {
        int dt = blockIdx.x * NBLK + nt * NTILE;

        __syncthreads();   // previous tile's K-loop done before overwriting B
        // ---- load B tile: 64 dims x 256 k, hi+lo (packed bf16 uint4 in gmem) ----
        #pragma unroll
        for (int i = 0; i < 8; i++) {
            int e  = tid + i * 256;       // group index 0..2047
            int n  = e >> 5;
            int k0 = (e & 31) << 3;
            int u  = ((dt + n) << 5) + (k0 >> 3);   // uint4 index into g_B*4
            uint32_t o = sw_off(n, k0);
            *(uint4*)(smem + B_HI + o) = g_BH4[u];
            *(uint4*)(smem + B_LO + o) = g_BL4[u];
        }
        __syncthreads();

        float acc[2][2][4];
        #pragma unroll
        for (int mf = 0; mf < 2; mf++)
            #pragma unroll
            for (int nf = 0; nf < 2; nf++)
                #pragma unroll
                for (int q = 0; q < 4; q++) acc[mf][nf][q] = 0.f;

        #pragma unroll
        for (int k16 = 0; k16 < 16; k16++) {
            int k0 = k16 << 4;
            uint32_t ah0[4], ah1[4], al0[4], al1[4], bh[4], bl[4];
            uint32_t ao0 = sw_off(am_base,      k0 + ak_add);
            uint32_t ao1 = sw_off(am_base + 16, k0 + ak_add);
            uint32_t bo  = sw_off(bn_base,      k0 + bk_add);
            ldm4(ah0, sb + A_HI + ao0);
            ldm4(ah1, sb + A_HI + ao1);
            ldm4(bh,  sb + B_HI + bo);
            ldm4(al0, sb + A_LO + ao0);
            ldm4(al1, sb + A_LO + ao1);
            ldm4(bl,  sb + B_LO + bo);

            // D += Ah*Bh + Ah*Bl + Al*Bh   (fp32 accumulate)
            mma16816(acc[0][0], ah0, bh);     mma16816(acc[0][1], ah0, bh + 2);
            mma16816(acc[1][0], ah1, bh);     mma16816(acc[1][1], ah1, bh + 2);
            mma16816(acc[0][0], ah0, bl);     mma16816(acc[0][1], ah0, bl + 2);
            mma16816(acc[1][0], ah1, bl);     mma16816(acc[1][1], ah1, bl + 2);
            mma16816(acc[0][0], al0, bh);     mma16816(acc[0][1], al0, bh + 2);
            mma16816(acc[1][0], al1, bh);     mma16816(acc[1][1], al1, bh + 2);
        }

        // ---- epilogue: scatter D rows via s_pos ----
        #pragma unroll
        for (int mf = 0; mf < 2; mf++) {
            int mrow = wm * 32 + mf * 16 + (lane >> 2);
            int p0 = s_pos[mrow];
            int p1 = s_pos[mrow + 8];
            #pragma unroll
            for (int nf = 0; nf < 2; nf++) {
                int col = dt + wn * 16 + nf * 8 + (lane & 3) * 2;
                if (p0 >= 0)
                    *(float2*)(out + (size_t)p0 * D + col) =
                        make_float2(acc[mf][nf][0], acc[mf][nf][1]);
                if (p1 >= 0)
                    *(float2*)(out + (size_t)p1 * D + col) =
                        make_float2(acc[mf][nf][2], acc[mf][nf][3]);
            }
        }
    }
}

// ---------------- launcher ----------------
extern "C" void kernel_launch(void* const* d_in, const int* in_sizes, int n_in,
                              void* d_out, int out_size) {
    const int*   x        = (const int*)d_in[0];
    const float* tok_emb  = (const float*)d_in[1];
    const float* added    = (const float*)d_in[2];
    const float* nums     = (const float*)d_in[3];
    const float* codebook = (const float*)d_in[4];
    const float* proj_w   = (const float*)d_in[5];
    float*       out      = (float*)d_out;
    int n_tok = in_sizes[0];

    cudaFuncSetAttribute(img_hmma_kernel,
                         cudaFuncAttributeMaxDynamicSharedMemorySize, SMEM_BYTES);

    split_kernel<<<(D * VQD / 8 + 255) / 256, 256>>>((const float4*)proj_w);

    classify_copy_kernel<<<(n_tok + 7) / 8, 256>>>(
        x, (const float4*)tok_emb, (const float4*)added,
        (const float4*)nums, (float4*)out, n_tok);

    int mtiles = (n_tok + GT - 1) / GT;     // worst case: all tokens are images
    img_hmma_kernel<<<dim3(NSPLIT, mtiles), 256, SMEM_BYTES>>>(codebook, out);
}

// round 16
// speedup vs baseline: 1.7302x; 1.0029x over previous
#include <cuda_runtime.h>
#include <cuda_bf16.h>
#include <cstdint>

// ---------------- problem constants ----------------
#define D        2048     // EMBED_DIM
#define VQD      256      // VQ_DIM
#define ATO      32000
#define NUMLIM   33000    // ATO + SCO
#define TDLIM    33100    // VQ_START / image_token_offset
#define VQEND    49484
#define NTOK_MAX 65536

// ---------------- scratch (no allocations allowed) ----------------
__device__ int g_cnt;
__device__ int g_pos[NTOK_MAX];
__device__ int g_idx[NTOK_MAX];
// proj_w split into bf16 hi/lo, layout [d][k] (k contiguous), packed 8 bf16
// per uint4. uint4 typing guarantees 16B alignment BY TYPE (the __align__
// attribute on a bf16 array was not honored -> misaligned address in R13/R14).
__device__ uint4 g_BH4[D * VQD / 8];
__device__ uint4 g_BL4[D * VQD / 8];

__device__ __forceinline__ uint32_t pbf2(float a, float b) {
    __nv_bfloat162 h = __floats2bfloat162_rn(a, b);
    return *(uint32_t*)&h;
}

// ---------------- launch 1: split proj_w -> bf16 hi/lo (packed) + zero counter ----------------
__global__ void split_kernel(const float4* __restrict__ proj_w4) {
    int i = blockIdx.x * blockDim.x + threadIdx.x;    // uint4 index (8 floats)
    if (i == 0) g_cnt = 0;
    if (i < D * VQD / 8) {
        float4 v0 = proj_w4[2 * i];
        float4 v1 = proj_w4[2 * i + 1];
        float f[8] = {v0.x, v0.y, v0.z, v0.w, v1.x, v1.y, v1.z, v1.w};
        uint32_t h[4], l[4];
        #pragma unroll
        for (int p = 0; p < 4; p++) {
            float a = f[2 * p], b = f[2 * p + 1];
            float ah = __bfloat162float(__float2bfloat16_rn(a));
            float bh = __bfloat162float(__float2bfloat16_rn(b));
            h[p] = pbf2(a, b);
            l[p] = pbf2(a - ah, b - bh);
        }
        g_BH4[i] = make_uint4(h[0], h[1], h[2], h[3]);
        g_BL4[i] = make_uint4(l[0], l[1], l[2], l[3]);
    }
}

// ---------------- launch 2: classify + gather-copy (warp per token) ----------------
__global__ void classify_copy_kernel(const int* __restrict__ x,
                                     const float4* __restrict__ tok_emb,
                                     const float4* __restrict__ added_emb,
                                     const float4* __restrict__ nums_emb,
                                     float4* __restrict__ out, int n_tok) {
    int gw   = (blockIdx.x * blockDim.x + threadIdx.x) >> 5;
    int lane = threadIdx.x & 31;
    if (gw >= n_tok) return;
    int t = x[gw];

    const float4* src;
    if (t < ATO) {
        src = tok_emb + (size_t)t * (D / 4);
    } else if (t < NUMLIM) {
        src = nums_emb + (size_t)(t - ATO) * (D / 4);
    } else if (t < TDLIM) {
        src = added_emb + (size_t)(t - NUMLIM) * (D / 4);
    } else if (t < VQEND) {
        if (lane == 0) {
            int s = atomicAdd(&g_cnt, 1);
            g_pos[s] = gw;
            g_idx[s] = t - TDLIM;
        }
        return;
    } else {
        src = nullptr;
    }

    float4* dst = out + (size_t)gw * (D / 4);
    if (src) {
        #pragma unroll
        for (int i = 0; i < (D / 4) / 32; i++)
            dst[lane + 32 * i] = src[lane + 32 * i];
    } else {
        float4 z = make_float4(0.f, 0.f, 0.f, 0.f);
        #pragma unroll
        for (int i = 0; i < (D / 4) / 32; i++)
            dst[lane + 32 * i] = z;
    }
}

// ---------------- launch 3: HMMA (mma.sync bf16, 3-term split) image GEMM ----------------
// Block: 64 tokens x 1024 dims (grid.x splits D in 2). Inner loop: 16 tiles of 64 dims.
// 8 warps as 2(m) x 4(n): warp tile m32 x n16. K = 256 in 16 k16-steps.
#define GT      64
#define NSPLIT  2
#define NBLK    (D / NSPLIT)   // 1024
#define NTILE   64

// smem plane offsets (bytes)
#define A_HI 0
#define A_LO 32768
#define B_HI 65536
#define B_LO 98304
#define SMEM_BYTES 131072

// XOR-swizzled offset within one 32KB plane: 64 rows x 256 k (bf16), stored as
// 4 k-chunks of 64; within a chunk, 8x16B groups per row, group ^= (row & 7).
__device__ __forceinline__ uint32_t sw_off(int row, int k) {
    return ((uint32_t)(k >> 6) << 13) + ((uint32_t)row << 7)
         + ((uint32_t)((((k >> 3) & 7) ^ (row & 7))) << 4) + ((uint32_t)(k & 7) << 1);
}

__device__ __forceinline__ uint32_t smem_u32(const void* p) {
    uint32_t a;
    asm("{ .reg .u64 t; cvta.to.shared.u64 t, %1; cvt.u32.u64 %0, t; }" : "=r"(a) : "l"(p));
    return a;
}
__device__ __forceinline__ void ldm4(uint32_t* r, uint32_t addr) {
    asm volatile("ldmatrix.sync.aligned.m8n8.x4.shared.b16 {%0,%1,%2,%3}, [%4];"
        : "=r"(r[0]), "=r"(r[1]), "=r"(r[2]), "=r"(r[3]) : "r"(addr));
}
__device__ __forceinline__ void mma16816(float* c, const uint32_t* a, const uint32_t* b) {
    asm volatile("mma.sync.aligned.m16n8k16.row.col.f32.bf16.bf16.f32 "
        "{%0,%1,%2,%3}, {%4,%5,%6,%7}, {%8,%9}, {%0,%1,%2,%3};"
        : "+f"(c[0]), "+f"(c[1]), "+f"(c[2]), "+f"(c[3])
        : "r"(a[0]), "r"(a[1]), "r"(a[2]), "r"(a[3]), "r"(b[0]), "r"(b[1]));
}

__global__ void __launch_bounds__(256, 1)
img_hmma_kernel(const float* __restrict__ codebook, float* __restrict__ out) {
    extern __shared__ __align__(16) char smem[];
    __shared__ int s_pos[GT];

    int n_img = g_cnt;
    int t0 = blockIdx.y * GT;
    if (t0 >= n_img) return;

    uint32_t sb = smem_u32(smem);
    int tid  = threadIdx.x;
    int lane = tid & 31;
    int wid  = tid >> 5;
    int wm   = wid >> 2;          // 0..1 -> m offset 0/32
    int wn   = wid & 3;           // 0..3 -> n offset 0/16/32/48

    if (tid < GT) {
        int gi = t0 + tid;
        s_pos[tid] = (gi < n_img) ? g_pos[gi] : -1;
    }

    // ---- gather A (codebook rows), split into bf16 hi/lo, swizzled smem ----
    #pragma unroll
    for (int i = 0; i < 8; i++) {
        int e  = tid + i * 256;           // 0..2047 ; each handles 8 floats
        int m  = e >> 5;                  // token within block
        int k0 = (e & 31) << 3;           // k start (mult of 8)
        int gi = t0 + m;
        int idx = (gi < n_img) ? g_idx[gi] : 0;
        const float4* src = (const float4*)(codebook + (size_t)idx * VQD + k0);
        float4 v0 = src[0];
        float4 v1 = src[1];
        float f[8] = {v0.x, v0.y, v0.z, v0.w, v1.x, v1.y, v1.z, v1.w};
        uint32_t h[4], l[4];
        #pragma unroll
        for (int p = 0; p < 4; p++) {
            float a = f[2 * p], b = f[2 * p + 1];
            float ah = __bfloat162float(__float2bfloat16_rn(a));
            float bh = __bfloat162float(__float2bfloat16_rn(b));
            h[p] = pbf2(a, b);
            l[p] = pbf2(a - ah, b - bh);
        }
        uint32_t o = sw_off(m, k0);
        *(uint4*)(smem + A_HI + o) = make_uint4(h[0], h[1], h[2], h[3]);
        *(uint4*)(smem + A_LO + o) = make_uint4(l[0], l[1], l[2], l[3]);
    }

    // per-lane ldmatrix address components
    int g = lane >> 3, r = lane & 7;
    int am_base = wm * 32 + ((g & 1) << 3) + r;       // A: g0/g2 -> m0-7, g1/g3 -> m8-15
    int ak_add  = (g >> 1) << 3;                      //    g2/g3 -> k+8
    int bn_base = wn * 16 + ((g >> 1) << 3) + r;      // B: g2/g3 -> n8-15
    int bk_add  = (g & 1) << 3;                       //    g1/g3 -> k+8

    for (int nt = 0; nt < NBLK / NTILE; nt++) {
        int dt = blockIdx.x * NBLK + nt * NTILE;

        __syncthreads();   // previous tile's K-loop done before overwriting B
        // ---- load B tile: 64 dims x 256 k, hi+lo (packed bf16 uint4 in gmem) ----
        #pragma unroll
        for (int i = 0; i < 8; i++) {
            int e  = tid + i * 256;       // group index 0..2047
            int n  = e >> 5;
            int k0 = (e & 31) << 3;
            int u  = ((dt + n) << 5) + (k0 >> 3);   // uint4 index into g_B*4
            uint32_t o = sw_off(n, k0);
            *(uint4*)(smem + B_HI + o) = g_BH4[u];
            *(uint4*)(smem + B_LO + o) = g_BL4[u];
        }
        __syncthreads();

        float acc[2][2][4];
        #pragma unroll
        for (int mf = 0; mf < 2; mf++)
            #pragma unroll
            for (int nf = 0; nf < 2; nf++)
                #pragma unroll
                for (int q = 0; q < 4; q++) acc[mf][nf][q] = 0.f;

        #pragma unroll
        for (int k16 = 0; k16 < 16; k16++) {
            int k0 = k16 << 4;
            uint32_t ah0[4], ah1[4], al0[4], al1[4], bh[4], bl[4];
            uint32_t ao0 = sw_off(am_base,      k0 + ak_add);
            uint32_t ao1 = sw_off(am_base + 16, k0 + ak_add);
            uint32_t bo  = sw_off(bn_base,      k0 + bk_add);
            ldm4(ah0, sb + A_HI + ao0);
            ldm4(ah1, sb + A_HI + ao1);
            ldm4(bh,  sb + B_HI + bo);
            ldm4(al0, sb + A_LO + ao0);
            ldm4(al1, sb + A_LO + ao1);
            ldm4(bl,  sb + B_LO + bo);

            // D += Ah*Bh + Ah*Bl + Al*Bh   (fp32 accumulate)
            mma16816(acc[0][0], ah0, bh);     mma16816(acc[0][1], ah0, bh + 2);
            mma16816(acc[1][0], ah1, bh);     mma16816(acc[1][1], ah1, bh + 2);
            mma16816(acc[0][0], ah0, bl);     mma16816(acc[0][1], ah0, bl + 2);
            mma16816(acc[1][0], ah1, bl);     mma16816(acc[1][1], ah1, bl + 2);
            mma16816(acc[0][0], al0, bh);     mma16816(acc[0][1], al0, bh + 2);
            mma16816(acc[1][0], al1, bh);     mma16816(acc[1][1], al1, bh + 2);
        }

        // ---- epilogue: scatter D rows via s_pos ----
        #pragma unroll
        for (int mf = 0; mf < 2; mf++) {
            int mrow = wm * 32 + mf * 16 + (lane >> 2);
            int p0 = s_pos[mrow];
            int p1 = s_pos[mrow + 8];
            #pragma unroll
            for (int nf = 0; nf < 2; nf++) {
                int col = dt + wn * 16 + nf * 8 + (lane & 3) * 2;
                if (p0 >= 0)
                    *(float2*)(out + (size_t)p0 * D + col) =
                        make_float2(acc[mf][nf][0], acc[mf][nf][1]);
                if (p1 >= 0)
                    *(float2*)(out + (size_t)p1 * D + col) =
                        make_float2(acc[mf][nf][2], acc[mf][nf][3]);
            }
        }
    }
}

// ---------------- launcher ----------------
extern "C" void kernel_launch(void* const* d_in, const int* in_sizes, int n_in,
                              void* d_out, int out_size) {
    const int*   x        = (const int*)d_in[0];
    const float* tok_emb  = (const float*)d_in[1];
    const float* added    = (const float*)d_in[2];
    const float* nums     = (const float*)d_in[3];
    const float* codebook = (const float*)d_in[4];
    const float* proj_w   = (const float*)d_in[5];
    float*       out      = (float*)d_out;
    int n_tok = in_sizes[0];

    cudaFuncSetAttribute(img_hmma_kernel,
                         cudaFuncAttributeMaxDynamicSharedMemorySize, SMEM_BYTES);

    split_kernel<<<(D * VQD / 8 + 255) / 256, 256>>>((const float4*)proj_w);

    classify_copy_kernel<<<(n_tok + 7) / 8, 256>>>(
        x, (const float4*)tok_emb, (const float4*)added,
        (const float4*)nums, (float4*)out, n_tok);

    int mtiles = (n_tok + GT - 1) / GT;     // worst case: all tokens are images
    img_hmma_kernel<<<dim3(NSPLIT, mtiles), 256, SMEM_BYTES>>>(codebook, out);
}